// round 4
// baseline (speedup 1.0000x reference)
#include <cuda_runtime.h>

// BWSGODE: 8192-step serial scalar ODE, single-thread issue-bound.
//
// v4: zero-forced-MOV f32x2 packing. Cost model (calibrated on v2/v3):
// cyc/iter ~= 2 x (fma-class instrs: FFMA/FMUL/FADD/FFMA2/MOV); STS/int are
// free fillers. v2 = 14 fp -> 28 cyc. Here: state kept as persistent pairs
// P={B,W}, Q={S,G}; only structurally mov-free pairs are packed:
//   {d1,a1} = fma2({p5,-p0}, Q, {-p7,p0})     (multiplicand IS Q)
//   {nB,nW} = fma2({g,e}, P, P)               (fresh scalars -> aligned pair)
//   {nS,nG} = fma2({b,a}, Q, Q)
// -> 11 fma-class ops/iter. Per-lane math bit-identical to v2.

__device__ __forceinline__ unsigned long long pk2(float lo, float hi) {
    unsigned long long r;
    asm("mov.b64 %0, {%1, %2};" : "=l"(r) : "f"(lo), "f"(hi));
    return r;
}
__device__ __forceinline__ void upk2(unsigned long long v, float& lo, float& hi) {
    asm("mov.b64 {%0, %1}, %2;" : "=f"(lo), "=f"(hi) : "l"(v));
}
__device__ __forceinline__ unsigned long long fma2(unsigned long long a,
                                                   unsigned long long b,
                                                   unsigned long long c) {
    unsigned long long d;
    asm("fma.rn.f32x2 %0, %1, %2, %3;" : "=l"(d) : "l"(a), "l"(b), "l"(c));
    return d;
}

__global__ void __launch_bounds__(256, 1)
bwsg_ode_kernel(const float* __restrict__ y0,
                const float* __restrict__ p,
                float* __restrict__ out,
                int num_steps) {
    extern __shared__ unsigned long long traj[];  // 2 x u64 per step = float4

    if (threadIdx.x == 0) {
        float B = y0[0];
        float W = y0[1];
        float S = y0[2];
        float G = y0[3];
        const float iv = y0[4];

        const float p0 = p[0], p2 = p[2], p5 = p[5], p8 = p[8];
        const float np1 = -p[1], np3 = -p[3], np4 = -p[4];
        const float np6 = -p[6], np7 = -p[7], np9 = -p[9];
        const float np0 = -p0;

        const float fi  = (iv != 0.0f) ? 1.0f : 0.0f;
        const float thr = __fsub_rn(__fadd_rn(5.0f, iv), 1.0f);

        // First integer step with mask==1 (ceil of threshold; exact for ints).
        int j0 = 1;
        if (fi != 0.0f) {
            float ct = ceilf(thr);
            if (ct > 1.0f) {
                j0 = (ct >= (float)num_steps) ? num_steps : (int)ct;
            }
        }

        traj[0] = pk2(B, W);
        traj[1] = pk2(S, G);

        // ---- Phase 1: mask == 0 (interventional only), B frozen ----
        for (int j = 1; j < j0; ++j) {
            float a = __fmaf_rn(np0, G, p0);
            a       = __fmaf_rn(np1, S, a);
            float c = __fmaf_rn(p2, G, np4);
            float b = __fmaf_rn(np3, W, c);
            float d = __fmaf_rn(p5, S, np7);
            float e = __fmul_rn(W, d);
            float nS = __fmaf_rn(b, S, S);
            float nW = __fmaf_rn(e, W, W);
            float nG = __fmaf_rn(a, G, G);
            W = nW; S = nS; G = nG;
            traj[2 * j]     = pk2(B, W);
            traj[2 * j + 1] = pk2(S, G);
        }

        // ---- Phase 2: mask == 1, hot loop: 11 fma-class ops ----
        const unsigned long long C_m1 = pk2(p5, np0);   // {p5, -p0}
        const unsigned long long C_a1 = pk2(np7, p0);   // {-p7, p0}

        unsigned long long P = pk2(B, W);   // {B, W}
        unsigned long long Q = pk2(S, G);   // {S, G}

        #pragma unroll 8
        for (int j = j0; j < num_steps; ++j) {
            float lB, lW, lS, lG;
            upk2(P, lB, lW);               // register aliases, no SASS
            upk2(Q, lS, lG);

            // {d1, a1} = {p5*S - p7, p0 - p0*G}
            unsigned long long D1A1 = fma2(C_m1, Q, C_a1);
            float d1, a1;
            upk2(D1A1, d1, a1);

            float a = __fmaf_rn(np1, lS, a1);   // a1 - p1*S
            float t = __fadd_rn(lW, lB);        // W + B
            float c = __fmaf_rn(p2, lG, np4);   // p2*G - p4
            float b = __fmaf_rn(np3, t, c);     // c - p3*t
            float d = __fmaf_rn(np6, lB, d1);   // d1 - p6*B
            float e = __fmul_rn(lW, d);         // W*d
            float f = __fadd_rn(lS, lW);        // S + W
            float g = __fmaf_rn(p8, f, np9);    // p8*f - p9

            P = fma2(pk2(g, e), P, P);          // {B+g*B, W+e*W}
            Q = fma2(pk2(b, a), Q, Q);          // {S+b*S, G+a*G}

            traj[2 * j]     = P;                // 2 x STS.64 (lsu, free slots)
            traj[2 * j + 1] = Q;
        }
    }

    __syncthreads();

    // Parallel fan-out: shared (num_steps x float4 {B,W,S,G}) -> (num_steps,5).
    const float iv = y0[4];
    const float4* tr4 = (const float4*)traj;
    for (int r = threadIdx.x; r < num_steps; r += blockDim.x) {
        const float4 s = tr4[r];
        float* o = out + (size_t)r * 5;
        o[0] = s.x;
        o[1] = s.y;
        o[2] = s.z;
        o[3] = s.w;
        o[4] = iv;
    }
}

extern "C" void kernel_launch(void* const* d_in, const int* in_sizes, int n_in,
                              void* d_out, int out_size) {
    const float* y0     = (const float*)d_in[0];
    const float* params = (const float*)d_in[1];
    const int num_steps = out_size / 5;

    const size_t smem = (size_t)num_steps * 16;
    cudaFuncSetAttribute(bwsg_ode_kernel,
                         cudaFuncAttributeMaxDynamicSharedMemorySize,
                         (int)smem);
    bwsg_ode_kernel<<<1, 256, smem>>>(y0, params, (float*)d_out, num_steps);
}

// round 5
// speedup vs baseline: 1.3855x; 1.3855x over previous
#include <cuda_runtime.h>

// BWSGODE: 8192-step serial scalar ODE, single-thread issue-bound.
//
// v5 = v2 (best, 126 us) + FFMA-imm for the two plain adds.
// Cost model (validated r2-r4): cyc/iter = sum of fma-pipe issue slots;
// 3-reg FFMA/FMUL/FADD cost 2, FFMA-with-immediate-multiplier costs 1
// (rt_SMSP=1). STS/IADD/BRA ride other pipes for free.
//   t = W + B  ->  fma.rn.f32 t, W, 1.0, B   (bit-exact: 1.0*x is exact)
//   f = S + W  ->  fma.rn.f32 f, S, 1.0, W
// 12x2 + 2x1 = 26 cyc/iter floor (dep chain 16 cyc, non-binding).
// f32x2 packing abandoned: both attempts (r3, r4) regressed from MOV
// overhead + scheduling interference.

__device__ __forceinline__ float fadd_imm1(float x, float y) {
    // x*1.0f + y, forced into FFMA immediate-multiplier form (rt=1).
    float r;
    asm("fma.rn.f32 %0, %1, 0f3F800000, %2;" : "=f"(r) : "f"(x), "f"(y));
    return r;
}

__global__ void __launch_bounds__(256, 1)
bwsg_ode_kernel(const float* __restrict__ y0,
                const float* __restrict__ p,
                float* __restrict__ out,
                int num_steps) {
    extern __shared__ float4 traj[];  // num_steps entries (128 KB @ 8192)

    if (threadIdx.x == 0) {
        float B = y0[0];
        float W = y0[1];
        float S = y0[2];
        float G = y0[3];
        const float iv = y0[4];

        const float p0 = p[0], p2 = p[2], p5 = p[5], p8 = p[8];
        const float np1 = -p[1], np3 = -p[3], np4 = -p[4];
        const float np6 = -p[6], np7 = -p[7], np9 = -p[9];
        const float np0 = -p0;

        const float fi  = (iv != 0.0f) ? 1.0f : 0.0f;
        const float thr = __fsub_rn(__fadd_rn(5.0f, iv), 1.0f);

        // First integer step with mask==1 (j >= thr <=> j >= ceil(thr) for
        // integer j; fp compare of exact integers is exact).
        int j0 = 1;
        if (fi != 0.0f) {
            float ct = ceilf(thr);
            if (ct > 1.0f) {
                j0 = (ct >= (float)num_steps) ? num_steps : (int)ct;
            }
        }

        traj[0] = make_float4(B, W, S, G);

        // ---- Phase 1: mask == 0 (interventional only), B frozen ----
        for (int j = 1; j < j0; ++j) {
            float a = __fmaf_rn(np0, G, p0);
            a       = __fmaf_rn(np1, S, a);
            float c = __fmaf_rn(p2, G, np4);
            float b = __fmaf_rn(np3, W, c);
            float d = __fmaf_rn(p5, S, np7);
            float e = __fmul_rn(W, d);
            float nS = __fmaf_rn(b, S, S);
            float nW = __fmaf_rn(e, W, W);
            float nG = __fmaf_rn(a, G, G);
            W = nW; S = nS; G = nG;
            traj[j] = make_float4(B, W, S, G);
        }

        // ---- Phase 2: mask == 1 hot loop: 12 reg-FFMA + 2 imm-FFMA ----
        #pragma unroll 8
        for (int j = j0; j < num_steps; ++j) {
            float a = __fmaf_rn(np0, G, p0);     // p0 - p0*G
            a       = __fmaf_rn(np1, S, a);      //   - p1*S
            float t = fadd_imm1(W, B);           // W + B   (FFMA-imm, rt=1)
            float c = __fmaf_rn(p2, G, np4);     // p2*G - p4
            float b = __fmaf_rn(np3, t, c);      //   - p3*(W+B)
            float d = __fmaf_rn(p5, S, np7);     // p5*S - p7
            d       = __fmaf_rn(np6, B, d);      //   - p6*B
            float e = __fmul_rn(W, d);           // W*(...)
            float f = fadd_imm1(S, W);           // S + W   (FFMA-imm, rt=1)
            float g = __fmaf_rn(p8, f, np9);     // p8*(S+W) - p9
            float nB = __fmaf_rn(g, B, B);       // B += dB
            float nW = __fmaf_rn(e, W, W);       // W += dW
            float nS = __fmaf_rn(b, S, S);       // S += dS
            float nG = __fmaf_rn(a, G, G);       // G += dG
            B = nB; W = nW; S = nS; G = nG;
            traj[j] = make_float4(B, W, S, G);   // STS.128 (LSU, free slot)
        }
    }

    __syncthreads();

    // Parallel fan-out: shared (num_steps x float4) -> global (num_steps, 5),
    // column 4 = i.
    const float iv = y0[4];
    for (int r = threadIdx.x; r < num_steps; r += blockDim.x) {
        const float4 s = traj[r];
        float* o = out + (size_t)r * 5;
        o[0] = s.x;
        o[1] = s.y;
        o[2] = s.z;
        o[3] = s.w;
        o[4] = iv;
    }
}

extern "C" void kernel_launch(void* const* d_in, const int* in_sizes, int n_in,
                              void* d_out, int out_size) {
    const float* y0     = (const float*)d_in[0];
    const float* params = (const float*)d_in[1];
    const int num_steps = out_size / 5;

    const size_t smem = (size_t)num_steps * sizeof(float4);
    cudaFuncSetAttribute(bwsg_ode_kernel,
                         cudaFuncAttributeMaxDynamicSharedMemorySize,
                         (int)smem);
    bwsg_ode_kernel<<<1, 256, smem>>>(y0, params, (float*)d_out, num_steps);
}

// round 6
// speedup vs baseline: 1.4082x; 1.0164x over previous
#include <cuda_runtime.h>

// BWSGODE: 8192-step serial scalar ODE, single-thread issue-bound.
//
// v6 = v2 loop (bit-exact, proven 126.2us / 28.3 cyc/iter = the 14-op x
// 2-cyc issue floor on sm_100a) + producer/consumer overlap of the global
// writeback:
//   - thread 0: serial recurrence -> shared traj, publishes progress every
//     512 rows (volatile smem counter + __threadfence_block).
//   - warps 1..7: per completed chunk, stream shared -> global as coalesced
//     STG.128 over the flat (num_steps*5) float array; __nanosleep-throttled
//     spin so polling doesn't steal warp-0 SMSP issue slots.
//   - warp 0 lanes 1..31 exit immediately (no divergence inside the
//     producer warp).
// f32x2 packing (r3,r4) and FFMA-imm (r5) are confirmed dead on sm_100a.

#define CHUNK_LOG2 9
#define CHUNK (1 << CHUNK_LOG2)

__shared__ volatile int s_progress;

__global__ void __launch_bounds__(256, 1)
bwsg_ode_kernel(const float* __restrict__ y0,
                const float* __restrict__ p,
                float* __restrict__ out,
                int num_steps) {
    extern __shared__ float4 traj[];  // num_steps entries (128 KB @ 8192)

    const int tid = threadIdx.x;
    if (tid == 0) s_progress = 0;
    __syncthreads();  // the ONLY block-wide sync; everything after is P/C.

    const float iv = y0[4];

    if (tid == 0) {
        // ---------------- producer: the serial recurrence ----------------
        float B = y0[0];
        float W = y0[1];
        float S = y0[2];
        float G = y0[3];

        const float p0 = p[0], p2 = p[2], p5 = p[5], p8 = p[8];
        const float np1 = -p[1], np3 = -p[3], np4 = -p[4];
        const float np6 = -p[6], np7 = -p[7], np9 = -p[9];
        const float np0 = -p0;

        const float fi  = (iv != 0.0f) ? 1.0f : 0.0f;
        const float thr = __fsub_rn(__fadd_rn(5.0f, iv), 1.0f);

        // First integer step with mask==1 (j >= thr <=> j >= ceil(thr) for
        // integer j; fp compare of exact integers is exact).
        int j0 = 1;
        if (fi != 0.0f) {
            float ct = ceilf(thr);
            if (ct > 1.0f) {
                j0 = (ct >= (float)num_steps) ? num_steps : (int)ct;
            }
        }

        traj[0] = make_float4(B, W, S, G);

        // ---- Phase 1: mask == 0 (interventional only), B frozen ----
        for (int j = 1; j < j0; ++j) {
            float a = __fmaf_rn(np0, G, p0);
            a       = __fmaf_rn(np1, S, a);
            float c = __fmaf_rn(p2, G, np4);
            float b = __fmaf_rn(np3, W, c);
            float d = __fmaf_rn(p5, S, np7);
            float e = __fmul_rn(W, d);
            float nS = __fmaf_rn(b, S, S);
            float nW = __fmaf_rn(e, W, W);
            float nG = __fmaf_rn(a, G, G);
            W = nW; S = nS; G = nG;
            traj[j] = make_float4(B, W, S, G);
        }

        // ---- Phase 2: mask == 1 hot loop (14 fp ops), chunk-published ----
        int j = j0;
        while (j < num_steps) {
            const int end = min((((j >> CHUNK_LOG2) + 1) << CHUNK_LOG2),
                                num_steps);
            #pragma unroll 8
            for (; j < end; ++j) {
                float a = __fmaf_rn(np0, G, p0);     // p0 - p0*G
                a       = __fmaf_rn(np1, S, a);      //   - p1*S
                float t = __fadd_rn(W, B);           // W + B
                float c = __fmaf_rn(p2, G, np4);     // p2*G - p4
                float b = __fmaf_rn(np3, t, c);      //   - p3*(W+B)
                float d = __fmaf_rn(p5, S, np7);     // p5*S - p7
                d       = __fmaf_rn(np6, B, d);      //   - p6*B
                float e = __fmul_rn(W, d);           // W*(...)
                float f = __fadd_rn(S, W);           // S + W
                float g = __fmaf_rn(p8, f, np9);     // p8*(S+W) - p9
                float nB = __fmaf_rn(g, B, B);
                float nW = __fmaf_rn(e, W, W);
                float nS = __fmaf_rn(b, S, S);
                float nG = __fmaf_rn(a, G, G);
                B = nB; W = nW; S = nS; G = nG;
                traj[j] = make_float4(B, W, S, G);   // STS.128 (hidden)
            }
            __threadfence_block();
            s_progress = end;
        }
        __threadfence_block();
        s_progress = num_steps;  // covers j0 == num_steps and the tail
    } else if (tid >= 32) {
        // ---------------- consumers: chunked coalesced writeback ---------
        const int ct  = tid - 32;        // 0..223
        const int ncs = 224;
        const float* tf = (const float*)traj;       // flat smem floats
        float4* o4 = (float4*)out;

        const int total_f  = num_steps * 5;
        const int total_f4 = total_f >> 2;
        const int n_chunks = (num_steps + CHUNK - 1) >> CHUNK_LOG2;
        const int f4_per_chunk = (CHUNK * 5) >> 2;  // 640

        for (int k = 0; k < n_chunks; ++k) {
            const int rows_done = min((k + 1) << CHUNK_LOG2, num_steps);
            while (s_progress < rows_done) __nanosleep(64);
            __threadfence_block();  // acquire: traj data before flag

            const int m0 = k * f4_per_chunk;
            const int m1 = min(m0 + f4_per_chunk, total_f4);
            for (int m = m0 + ct; m < m1; m += ncs) {
                const int n = m << 2;
                float v[4];
                #pragma unroll
                for (int e = 0; e < 4; ++e) {
                    const int ne = n + e;
                    const int r  = ne / 5;
                    const int c  = ne - r * 5;
                    v[e] = (c == 4) ? iv : tf[(r << 2) + c];
                }
                o4[m] = make_float4(v[0], v[1], v[2], v[3]);  // STG.128
            }
        }
        // scalar tail if num_steps*5 % 4 != 0 (not hit at 8192, kept general)
        if (ct == 0) {
            for (int ne = total_f4 << 2; ne < total_f; ++ne) {
                const int r = ne / 5;
                const int c = ne - r * 5;
                out[ne] = (c == 4) ? iv : tf[(r << 2) + c];
            }
        }
    }
    // warp 0, lanes 1..31: fall through and exit.
}

extern "C" void kernel_launch(void* const* d_in, const int* in_sizes, int n_in,
                              void* d_out, int out_size) {
    const float* y0     = (const float*)d_in[0];
    const float* params = (const float*)d_in[1];
    const int num_steps = out_size / 5;

    const size_t smem = (size_t)num_steps * sizeof(float4);
    cudaFuncSetAttribute(bwsg_ode_kernel,
                         cudaFuncAttributeMaxDynamicSharedMemorySize,
                         (int)smem);
    bwsg_ode_kernel<<<1, 256, smem>>>(y0, params, (float*)d_out, num_steps);
}

// round 7
// speedup vs baseline: 1.4578x; 1.0352x over previous
#include <cuda_runtime.h>

// BWSGODE: 8192-step serial scalar ODE, single-thread issue-bound.
//
// v7 = v6 (bit-exact producer/consumer overlap) + SMSP-0 isolation.
// Floor analysis (validated r2-r6): the 4 multipliers are affine forms with
// (3,4,3,3) terms + 4 update FMAs = 14 fma-pipe ops, irreducible; one warp
// issues fma ops at rt=2 -> 28 cyc/iter hard floor ~= 124us.
// Remaining lever: intra-SMSP arbitration is highest-wid-first, and warp 4
// (wid%4==0) shares SMSP 0 with the producer warp 0 and OUTRANKS it — its
// polls and copy bursts preempt producer issue slots. So consumers are now
// warps 1,2,3,5,6,7 only (192 threads); warp 4 exits immediately. Poll
// sleep raised to 256ns.

#define CHUNK_LOG2 9
#define CHUNK (1 << CHUNK_LOG2)

__shared__ volatile int s_progress;

__global__ void __launch_bounds__(256, 1)
bwsg_ode_kernel(const float* __restrict__ y0,
                const float* __restrict__ p,
                float* __restrict__ out,
                int num_steps) {
    extern __shared__ float4 traj[];  // num_steps entries (128 KB @ 8192)

    const int tid = threadIdx.x;
    const int wid = tid >> 5;
    if (tid == 0) s_progress = 0;
    __syncthreads();  // the ONLY block-wide sync; everything after is P/C.

    const float iv = __ldg(&y0[4]);

    if (tid == 0) {
        // ---------------- producer: the serial recurrence ----------------
        float B = __ldg(&y0[0]);
        float W = __ldg(&y0[1]);
        float S = __ldg(&y0[2]);
        float G = __ldg(&y0[3]);

        const float p0 = p[0], p2 = p[2], p5 = p[5], p8 = p[8];
        const float np1 = -p[1], np3 = -p[3], np4 = -p[4];
        const float np6 = -p[6], np7 = -p[7], np9 = -p[9];
        const float np0 = -p0;

        const float fi  = (iv != 0.0f) ? 1.0f : 0.0f;
        const float thr = __fsub_rn(__fadd_rn(5.0f, iv), 1.0f);

        // First integer step with mask==1 (j >= thr <=> j >= ceil(thr) for
        // integer j; fp compare of exact integers is exact).
        int j0 = 1;
        if (fi != 0.0f) {
            float ct = ceilf(thr);
            if (ct > 1.0f) {
                j0 = (ct >= (float)num_steps) ? num_steps : (int)ct;
            }
        }

        traj[0] = make_float4(B, W, S, G);

        // ---- Phase 1: mask == 0 (interventional only), B frozen ----
        for (int j = 1; j < j0; ++j) {
            float a = __fmaf_rn(np0, G, p0);
            a       = __fmaf_rn(np1, S, a);
            float c = __fmaf_rn(p2, G, np4);
            float b = __fmaf_rn(np3, W, c);
            float d = __fmaf_rn(p5, S, np7);
            float e = __fmul_rn(W, d);
            float nS = __fmaf_rn(b, S, S);
            float nW = __fmaf_rn(e, W, W);
            float nG = __fmaf_rn(a, G, G);
            W = nW; S = nS; G = nG;
            traj[j] = make_float4(B, W, S, G);
        }

        // ---- Phase 2: mask == 1 hot loop (14 fp ops), chunk-published ----
        int j = j0;
        while (j < num_steps) {
            const int end = min((((j >> CHUNK_LOG2) + 1) << CHUNK_LOG2),
                                num_steps);
            #pragma unroll 8
            for (; j < end; ++j) {
                float a = __fmaf_rn(np0, G, p0);     // p0 - p0*G
                a       = __fmaf_rn(np1, S, a);      //   - p1*S
                float t = __fadd_rn(W, B);           // W + B
                float c = __fmaf_rn(p2, G, np4);     // p2*G - p4
                float b = __fmaf_rn(np3, t, c);      //   - p3*(W+B)
                float d = __fmaf_rn(p5, S, np7);     // p5*S - p7
                d       = __fmaf_rn(np6, B, d);      //   - p6*B
                float e = __fmul_rn(W, d);           // W*(...)
                float f = __fadd_rn(S, W);           // S + W
                float g = __fmaf_rn(p8, f, np9);     // p8*(S+W) - p9
                float nB = __fmaf_rn(g, B, B);
                float nW = __fmaf_rn(e, W, W);
                float nS = __fmaf_rn(b, S, S);
                float nG = __fmaf_rn(a, G, G);
                B = nB; W = nW; S = nS; G = nG;
                traj[j] = make_float4(B, W, S, G);   // STS.128 (hidden)
            }
            __threadfence_block();
            s_progress = end;
        }
        __threadfence_block();
        s_progress = num_steps;  // covers j0 == num_steps and the tail
    } else if (wid != 4 && tid >= 32) {
        // ------- consumers: warps 1,2,3,5,6,7 (SMSP 0 kept clear) --------
        const int ct  = (wid < 4) ? (tid - 32) : (tid - 64);  // 0..191
        const int ncs = 192;
        const float* tf = (const float*)traj;       // flat smem floats
        float4* o4 = (float4*)out;

        const int total_f  = num_steps * 5;
        const int total_f4 = total_f >> 2;
        const int n_chunks = (num_steps + CHUNK - 1) >> CHUNK_LOG2;
        const int f4_per_chunk = (CHUNK * 5) >> 2;  // 640

        for (int k = 0; k < n_chunks; ++k) {
            const int rows_done = min((k + 1) << CHUNK_LOG2, num_steps);
            while (s_progress < rows_done) __nanosleep(256);
            __threadfence_block();  // acquire: traj data before flag

            const int m0 = k * f4_per_chunk;
            const int m1 = min(m0 + f4_per_chunk, total_f4);
            for (int m = m0 + ct; m < m1; m += ncs) {
                const int n = m << 2;
                float v[4];
                #pragma unroll
                for (int e = 0; e < 4; ++e) {
                    const int ne = n + e;
                    const int r  = ne / 5;
                    const int c  = ne - r * 5;
                    v[e] = (c == 4) ? iv : tf[(r << 2) + c];
                }
                o4[m] = make_float4(v[0], v[1], v[2], v[3]);  // STG.128
            }
        }
        // scalar tail if num_steps*5 % 4 != 0 (not hit at 8192, kept general)
        if (ct == 0) {
            for (int ne = total_f4 << 2; ne < total_f; ++ne) {
                const int r = ne / 5;
                const int c = ne - r * 5;
                out[ne] = (c == 4) ? iv : tf[(r << 2) + c];
            }
        }
    }
    // warp 0 lanes 1..31 and all of warp 4: fall through and exit,
    // leaving SMSP 0's issue slots to the producer.
}

extern "C" void kernel_launch(void* const* d_in, const int* in_sizes, int n_in,
                              void* d_out, int out_size) {
    const float* y0     = (const float*)d_in[0];
    const float* params = (const float*)d_in[1];
    const int num_steps = out_size / 5;

    const size_t smem = (size_t)num_steps * sizeof(float4);
    cudaFuncSetAttribute(bwsg_ode_kernel,
                         cudaFuncAttributeMaxDynamicSharedMemorySize,
                         (int)smem);
    bwsg_ode_kernel<<<1, 256, smem>>>(y0, params, (float*)d_out, num_steps);
}